// round 9
// baseline (speedup 1.0000x reference)
#include <cuda_runtime.h>
#include <cstdint>

#define NN 100000
#define DD 128
#define EE_MAX 1700000

// Scratch (allocation-free rule: __device__ globals)
__device__ float g_h1[(size_t)NN * DD];
__device__ int   g_deg[NN];
__device__ int   g_cursor[NN];
__device__ int   g_rowptr[NN + 1];
__device__ int   g_col[EE_MAX];
__device__ int   g_partial[128];
__device__ int   g_total;

// ---------------------------------------------------------------------------
__global__ void deg_kernel(const int* __restrict__ dst, int E) {
    int e = blockIdx.x * blockDim.x + threadIdx.x;
    if (e < E) atomicAdd(&g_deg[dst[e]], 1);
}

// --- three-phase exclusive scan of g_deg -> g_rowptr.
// Also re-zeros g_deg (for next graph replay) and g_cursor (for fill).
__global__ __launch_bounds__(1024) void scanA_kernel(int n) {
    const int i = blockIdx.x * 1024 + threadIdx.x;
    const int lane = threadIdx.x & 31;
    const int w = threadIdx.x >> 5;
    const int v = (i < n) ? g_deg[i] : 0;
    int s = v;
#pragma unroll
    for (int o = 1; o < 32; o <<= 1) {
        int t = __shfl_up_sync(0xffffffffu, s, o);
        if (lane >= o) s += t;
    }
    __shared__ int wsum[32];
    if (lane == 31) wsum[w] = s;
    __syncthreads();
    if (w == 0) {
        int ws = wsum[lane];
#pragma unroll
        for (int o = 1; o < 32; o <<= 1) {
            int t = __shfl_up_sync(0xffffffffu, ws, o);
            if (lane >= o) ws += t;
        }
        wsum[lane] = ws;
    }
    __syncthreads();
    const int excl = s - v + (w ? wsum[w - 1] : 0);
    if (i < n) {
        g_rowptr[i] = excl;
        g_deg[i] = 0;       // ready for next replay
        g_cursor[i] = 0;    // ready for fill
    }
    if (threadIdx.x == 1023) g_partial[blockIdx.x] = excl + v;
}

__global__ __launch_bounds__(128) void scanB_kernel(int nb) {
    __shared__ int s[128];
    const int t = threadIdx.x;
    s[t] = (t < nb) ? g_partial[t] : 0;
    __syncthreads();
    for (int o = 1; o < 128; o <<= 1) {
        int x = (t >= o) ? s[t - o] : 0;
        __syncthreads();
        s[t] += x;
        __syncthreads();
    }
    g_partial[t] = t ? s[t - 1] : 0;
    if (t == 127) g_total = s[127];
}

__global__ void scanC_kernel(int n) {
    int i = blockIdx.x * blockDim.x + threadIdx.x;
    if (i < n) g_rowptr[i] += g_partial[i >> 10];
    if (i == n) g_rowptr[n] = g_total;
}

__global__ void fill_kernel(const int* __restrict__ src, const int* __restrict__ dst, int E) {
    int e = blockIdx.x * blockDim.x + threadIdx.x;
    if (e < E) {
        int d = dst[e];
        int p = atomicAdd(&g_cursor[d], 1);
        g_col[g_rowptr[d] + p] = src[e];
    }
}

// ---------------------------------------------------------------------------
// Fused gather-aggregate + single-pass TF32 mma.sync GEMM + bias(+relu).
// out[r][o] = relu?( mean_{s in N(r)} feat[s][:] @ Wn[o][:]
//                    + feat[r][:] @ Ws[o][:] + bn[o] + bs[o] )
// CTA: 128 rows x 128 cols x K256. Phase 1: each warp gathers 16 nodes'
// neighbor means directly into a persistent tf32 SMEM A-block (k 0..127,
// 4 chunk tiles). Phase 2: standard mainloop; chunks 0-3 read the persistent
// block, chunks 4-7 stage the self features from global.
// SMEM tile layout per 32-k chunk: [k4 (0..7)][row (pad 129)][c (0..3)].
__device__ __forceinline__ uint32_t f32_to_tf32(float a) {
    uint32_t r;
    asm("cvt.rna.tf32.f32 %0, %1;" : "=r"(r) : "f"(a));
    return r;
}
__device__ __forceinline__ void mma_tf32(float* d, const uint32_t* a, const uint32_t* b) {
    asm volatile(
        "mma.sync.aligned.m16n8k8.row.col.f32.tf32.tf32.f32 "
        "{%0,%1,%2,%3}, {%4,%5,%6,%7}, {%8,%9}, {%0,%1,%2,%3};"
        : "+f"(d[0]), "+f"(d[1]), "+f"(d[2]), "+f"(d[3])
        : "r"(a[0]), "r"(a[1]), "r"(a[2]), "r"(a[3]), "r"(b[0]), "r"(b[1]));
}

static constexpr int TILEF = 8 * 129 * 4;                 // floats per smem tile (4128)
static constexpr int GEMM_SMEM = 6 * TILEF * 4;           // 4 agg tiles + A-self + B

template <bool RELU>
__global__ __launch_bounds__(256) void gemm_fused_kernel(
    const float* __restrict__ feat, const float* __restrict__ Wn,
    const float* __restrict__ Ws, const float* __restrict__ bn,
    const float* __restrict__ bs, float* __restrict__ out, int n) {
    extern __shared__ float dsm[];
    float* sAgg = dsm;                 // 4 * TILEF (k = 0..127, tf32 agg)
    float* sA = dsm + 4 * TILEF;       // staging for self chunks
    float* sB = dsm + 5 * TILEF;

    const int tid = threadIdx.x;
    const int wid = tid >> 5;
    const int lane = tid & 31;
    const int block_row = blockIdx.x * 128;

    // ---- Phase 1: gather-aggregate 16 nodes per warp into sAgg ----
    {
        const int so_base = (lane >> 3) * TILEF + (lane & 7) * 516;
        const int cfeat = lane << 2;   // feature index of this lane's float4
#pragma unroll 1
        for (int i = 0; i < 16; i++) {
            const int row = wid * 16 + i;
            const int node = block_row + row;
            unsigned long long a01 = 0ull, a23 = 0ull;
            int degv = 0;
            if (node < n) {
                const int beg = g_rowptr[node];
                const int end = g_rowptr[node + 1];
                degv = end - beg;
                for (int base = beg; base < end; base += 32) {
                    const int idx = base + lane;
                    const int sv = (idx < end) ? g_col[idx] : 0;
                    const int cnt = min(end - base, 32);
#pragma unroll 4
                    for (int j = 0; j < cnt; j++) {
                        const int s = __shfl_sync(0xffffffffu, sv, j);
                        const ulonglong2 v =
                            *(const ulonglong2*)(feat + (size_t)s * DD + cfeat);
                        asm("add.rn.f32x2 %0, %0, %1;" : "+l"(a01) : "l"(v.x));
                        asm("add.rn.f32x2 %0, %0, %1;" : "+l"(a23) : "l"(v.y));
                    }
                }
            }
            const float inv = 1.0f / fmaxf((float)degv, 1.0f);
            float r0, r1, r2, r3;
            asm("mov.b64 {%0, %1}, %2;" : "=f"(r0), "=f"(r1) : "l"(a01));
            asm("mov.b64 {%0, %1}, %2;" : "=f"(r2), "=f"(r3) : "l"(a23));
            uint4 h;
            h.x = f32_to_tf32(r0 * inv);
            h.y = f32_to_tf32(r1 * inv);
            h.z = f32_to_tf32(r2 * inv);
            h.w = f32_to_tf32(r3 * inv);
            *(uint4*)(sAgg + so_base + row * 4) = h;
        }
    }
    __syncthreads();

    // ---- Phase 2: mainloop ----
    const int g = lane >> 2;       // group row 0..7
    const int c = lane & 3;        // col-in-group 0..3
    const int m0 = (wid >> 2) * 64;
    const int n0 = (wid & 3) * 32;

    float acc[4][4][4];
#pragma unroll
    for (int mt = 0; mt < 4; mt++)
#pragma unroll
        for (int nt = 0; nt < 4; nt++)
#pragma unroll
            for (int q = 0; q < 4; q++) acc[mt][nt][q] = 0.f;

    for (int c0 = 0; c0 < 256; c0 += 32) {
        const bool selfpart = (c0 >= 128);
        const float* bptr = selfpart ? (Ws + (c0 - 128)) : (Wn + c0);

        if (c0) __syncthreads();
        if (selfpart) {
            const float* aptr = feat + (size_t)block_row * DD + (c0 - 128);
#pragma unroll
            for (int i = 0; i < 4; i++) {
                const int f = i * 256 + tid;
                const int row = f >> 3;
                const int k4 = f & 7;
                const int so = k4 * 516 + row * 4;
                float4 va = make_float4(0.f, 0.f, 0.f, 0.f);
                if (block_row + row < n)
                    va = *(const float4*)(aptr + (size_t)row * DD + k4 * 4);
                uint4 h;
                h.x = f32_to_tf32(va.x);
                h.y = f32_to_tf32(va.y);
                h.z = f32_to_tf32(va.z);
                h.w = f32_to_tf32(va.w);
                *(uint4*)(sA + so) = h;
                const float4 vb = *(const float4*)(bptr + (size_t)row * 128 + k4 * 4);
                h.x = f32_to_tf32(vb.x);
                h.y = f32_to_tf32(vb.y);
                h.z = f32_to_tf32(vb.z);
                h.w = f32_to_tf32(vb.w);
                *(uint4*)(sB + so) = h;
            }
        } else {
#pragma unroll
            for (int i = 0; i < 4; i++) {
                const int f = i * 256 + tid;
                const int row = f >> 3;
                const int k4 = f & 7;
                const float4 vb = *(const float4*)(bptr + (size_t)row * 128 + k4 * 4);
                uint4 h;
                h.x = f32_to_tf32(vb.x);
                h.y = f32_to_tf32(vb.y);
                h.z = f32_to_tf32(vb.z);
                h.w = f32_to_tf32(vb.w);
                *(uint4*)(sB + k4 * 516 + row * 4) = h;
            }
        }
        __syncthreads();

        const float* aS = selfpart ? sA : (sAgg + (c0 >> 5) * TILEF);
#pragma unroll
        for (int s = 0; s < 4; s++) {
            const int kA = 2 * s, kB = 2 * s + 1;
            uint32_t Ah[4][4], Bh[4][2];
#pragma unroll
            for (int mt = 0; mt < 4; mt++) {
                const int r0 = m0 + mt * 16 + g;
                const int i00 = kA * 516 + r0 * 4 + c;
                const int i10 = kB * 516 + r0 * 4 + c;
                Ah[mt][0] = __float_as_uint(aS[i00]);
                Ah[mt][1] = __float_as_uint(aS[i00 + 32]);
                Ah[mt][2] = __float_as_uint(aS[i10]);
                Ah[mt][3] = __float_as_uint(aS[i10 + 32]);
            }
#pragma unroll
            for (int nt = 0; nt < 4; nt++) {
                const int nn = n0 + nt * 8 + g;
                Bh[nt][0] = __float_as_uint(sB[kA * 516 + nn * 4 + c]);
                Bh[nt][1] = __float_as_uint(sB[kB * 516 + nn * 4 + c]);
            }
#pragma unroll
            for (int mt = 0; mt < 4; mt++)
#pragma unroll
                for (int nt = 0; nt < 4; nt++)
                    mma_tf32(acc[mt][nt], Ah[mt], Bh[nt]);
        }
    }

    // Epilogue: bias + optional relu, float2 stores
#pragma unroll
    for (int nt = 0; nt < 4; nt++) {
        const int col = n0 + nt * 8 + 2 * c;
        const float b0v = bn[col] + bs[col];
        const float b1v = bn[col + 1] + bs[col + 1];
#pragma unroll
        for (int mt = 0; mt < 4; mt++) {
            const int r = block_row + m0 + mt * 16 + g;
            float v0 = acc[mt][nt][0] + b0v;
            float v1 = acc[mt][nt][1] + b1v;
            float v2 = acc[mt][nt][2] + b0v;
            float v3 = acc[mt][nt][3] + b1v;
            if (RELU) {
                v0 = fmaxf(v0, 0.f); v1 = fmaxf(v1, 0.f);
                v2 = fmaxf(v2, 0.f); v3 = fmaxf(v3, 0.f);
            }
            if (r < n)     *(float2*)(out + (size_t)r * DD + col) = make_float2(v0, v1);
            if (r + 8 < n) *(float2*)(out + (size_t)(r + 8) * DD + col) = make_float2(v2, v3);
        }
    }
}

// ---------------------------------------------------------------------------
extern "C" void kernel_launch(void* const* d_in, const int* in_sizes, int n_in,
                              void* d_out, int out_size) {
    const float* x   = (const float*)d_in[0];
    const int* ei    = (const int*)d_in[1];
    const float* Wn1 = (const float*)d_in[2];
    const float* bn1 = (const float*)d_in[3];
    const float* Ws1 = (const float*)d_in[4];
    const float* bs1 = (const float*)d_in[5];
    const float* Wn2 = (const float*)d_in[6];
    const float* bn2 = (const float*)d_in[7];
    const float* Ws2 = (const float*)d_in[8];
    const float* bs2 = (const float*)d_in[9];
    float* out = (float*)d_out;

    const int n = in_sizes[0] / DD;
    const int E = in_sizes[1] / 2;
    const int* src = ei;
    const int* dst = ei + E;

    float* d_h1;    cudaGetSymbolAddress((void**)&d_h1, g_h1);

    cudaFuncSetAttribute(gemm_fused_kernel<true>,
                         cudaFuncAttributeMaxDynamicSharedMemorySize, GEMM_SMEM);
    cudaFuncSetAttribute(gemm_fused_kernel<false>,
                         cudaFuncAttributeMaxDynamicSharedMemorySize, GEMM_SMEM);

    const int threads = 256;
    const int nb = (n + 1023) / 1024;

    // --- CSR build (deg/cursor re-zeroed inside scanA for replay) ---
    deg_kernel<<<(E + threads - 1) / threads, threads>>>(dst, E);
    scanA_kernel<<<nb, 1024>>>(n);
    scanB_kernel<<<1, 128>>>(nb);
    scanC_kernel<<<(n + 1 + threads - 1) / threads, threads>>>(n);
    fill_kernel<<<(E + threads - 1) / threads, threads>>>(src, dst, E);

    const int gemm_blocks = (n + 127) / 128;

    // layer 1: fused gather + GEMM + bias + relu -> h1
    gemm_fused_kernel<true><<<gemm_blocks, 256, GEMM_SMEM>>>(
        x, Wn1, Ws1, bn1, bs1, d_h1, n);

    // layer 2: fused gather + GEMM + bias -> out
    gemm_fused_kernel<false><<<gemm_blocks, 256, GEMM_SMEM>>>(
        d_h1, Wn2, Ws2, bn2, bs2, out, n);
}

// round 10
// speedup vs baseline: 1.1492x; 1.1492x over previous
#include <cuda_runtime.h>
#include <cstdint>

#define NN 100000
#define DD 128
#define EE_MAX 1700000

// Scratch (allocation-free rule: __device__ globals)
__device__ float g_agg[(size_t)NN * DD];
__device__ float g_h1[(size_t)NN * DD];
__device__ int   g_deg[NN];
__device__ int   g_cursor[NN];
__device__ int   g_rowptr[NN + 1];
__device__ int   g_col[EE_MAX];
__device__ int   g_partial[128];
__device__ int   g_total;

// Host-side stream/events for fork-join inside graph capture (created once at
// load time; no device-memory allocation involved).
static cudaStream_t g_s2;
static cudaEvent_t g_ev[4];
namespace {
struct _Init {
    _Init() {
        cudaStreamCreateWithFlags(&g_s2, cudaStreamNonBlocking);
        for (int i = 0; i < 4; i++)
            cudaEventCreateWithFlags(&g_ev[i], cudaEventDisableTiming);
    }
};
_Init _init;
}

// ---------------------------------------------------------------------------
__global__ void deg_kernel(const int* __restrict__ dst, int E) {
    int e = blockIdx.x * blockDim.x + threadIdx.x;
    if (e < E) atomicAdd(&g_deg[dst[e]], 1);
}

// --- three-phase exclusive scan of g_deg -> g_rowptr.
// Also re-zeros g_deg (next replay) and g_cursor (for fill).
__global__ __launch_bounds__(1024) void scanA_kernel(int n) {
    const int i = blockIdx.x * 1024 + threadIdx.x;
    const int lane = threadIdx.x & 31;
    const int w = threadIdx.x >> 5;
    const int v = (i < n) ? g_deg[i] : 0;
    int s = v;
#pragma unroll
    for (int o = 1; o < 32; o <<= 1) {
        int t = __shfl_up_sync(0xffffffffu, s, o);
        if (lane >= o) s += t;
    }
    __shared__ int wsum[32];
    if (lane == 31) wsum[w] = s;
    __syncthreads();
    if (w == 0) {
        int ws = wsum[lane];
#pragma unroll
        for (int o = 1; o < 32; o <<= 1) {
            int t = __shfl_up_sync(0xffffffffu, ws, o);
            if (lane >= o) ws += t;
        }
        wsum[lane] = ws;
    }
    __syncthreads();
    const int excl = s - v + (w ? wsum[w - 1] : 0);
    if (i < n) {
        g_rowptr[i] = excl;
        g_deg[i] = 0;
        g_cursor[i] = 0;
    }
    if (threadIdx.x == 1023) g_partial[blockIdx.x] = excl + v;
}

__global__ __launch_bounds__(128) void scanB_kernel(int nb) {
    __shared__ int s[128];
    const int t = threadIdx.x;
    s[t] = (t < nb) ? g_partial[t] : 0;
    __syncthreads();
    for (int o = 1; o < 128; o <<= 1) {
        int x = (t >= o) ? s[t - o] : 0;
        __syncthreads();
        s[t] += x;
        __syncthreads();
    }
    g_partial[t] = t ? s[t - 1] : 0;
    if (t == 127) g_total = s[127];
}

__global__ void scanC_kernel(int n) {
    int i = blockIdx.x * blockDim.x + threadIdx.x;
    if (i < n) g_rowptr[i] += g_partial[i >> 10];
    if (i == n) g_rowptr[n] = g_total;
}

__global__ void fill_kernel(const int* __restrict__ src, const int* __restrict__ dst, int E) {
    int e = blockIdx.x * blockDim.x + threadIdx.x;
    if (e < E) {
        int d = dst[e];
        int p = atomicAdd(&g_cursor[d], 1);
        g_col[g_rowptr[d] + p] = src[e];
    }
}

// ---------------------------------------------------------------------------
// Gather-side mean aggregation: one warp per node, pre-normalized by 1/deg.
__global__ __launch_bounds__(256) void agg_kernel(const float* __restrict__ feat,
                                                  float* __restrict__ out, int n) {
    const int warp = (blockIdx.x * blockDim.x + threadIdx.x) >> 5;
    if (warp >= n) return;
    const int lane = threadIdx.x & 31;
    const int c = lane << 2;
    const int beg = g_rowptr[warp];
    const int end = g_rowptr[warp + 1];

    unsigned long long a01 = 0ull, a23 = 0ull;
    for (int base = beg; base < end; base += 32) {
        const int idx = base + lane;
        const int sv = (idx < end) ? g_col[idx] : 0;
        const int cnt = min(end - base, 32);
#pragma unroll 4
        for (int j = 0; j < cnt; j++) {
            const int s = __shfl_sync(0xffffffffu, sv, j);
            const ulonglong2 v = *(const ulonglong2*)(feat + (size_t)s * DD + c);
            asm("add.rn.f32x2 %0, %0, %1;" : "+l"(a01) : "l"(v.x));
            asm("add.rn.f32x2 %0, %0, %1;" : "+l"(a23) : "l"(v.y));
        }
    }
    const float inv = 1.0f / fmaxf((float)(end - beg), 1.0f);
    float4 r;
    asm("mov.b64 {%0, %1}, %2;" : "=f"(r.x), "=f"(r.y) : "l"(a01));
    asm("mov.b64 {%0, %1}, %2;" : "=f"(r.z), "=f"(r.w) : "l"(a23));
    r.x *= inv; r.y *= inv; r.z *= inv; r.w *= inv;
    *(float4*)(out + (size_t)warp * DD + c) = r;
}

// ---------------------------------------------------------------------------
// Single-pass TF32 mma.sync half-GEMM (K=128).
// ADDPREV=false:  out[r][o] = A[r][:] @ W[o][:] + bn[o] + bs[o]
// ADDPREV=true :  out[r][o] = relu?( out[r][o] + A[r][:] @ W[o][:] )
// CTA: 128x128xK128, 8 warps (2m x 4n), warp tile 64x32, 4 K-chunks of 32.
// SMEM tile layout per chunk: [k4 (0..7)][row (pad 129)][c (0..3)] floats.
__device__ __forceinline__ uint32_t f32_to_tf32(float a) {
    uint32_t r;
    asm("cvt.rna.tf32.f32 %0, %1;" : "=r"(r) : "f"(a));
    return r;
}
__device__ __forceinline__ void mma_tf32(float* d, const uint32_t* a, const uint32_t* b) {
    asm volatile(
        "mma.sync.aligned.m16n8k8.row.col.f32.tf32.tf32.f32 "
        "{%0,%1,%2,%3}, {%4,%5,%6,%7}, {%8,%9}, {%0,%1,%2,%3};"
        : "+f"(d[0]), "+f"(d[1]), "+f"(d[2]), "+f"(d[3])
        : "r"(a[0]), "r"(a[1]), "r"(a[2]), "r"(a[3]), "r"(b[0]), "r"(b[1]));
}

static constexpr int TILEF = 8 * 129 * 4;                 // floats per smem tile
static constexpr int GEMM_SMEM = 2 * TILEF * 4;           // bytes (A + B)

template <bool RELU, bool ADDPREV>
__global__ __launch_bounds__(256) void gemm_half_kernel(
    const float* __restrict__ A, const float* __restrict__ W,
    const float* __restrict__ bn, const float* __restrict__ bs,
    float* __restrict__ out, int n) {
    extern __shared__ float dsm[];
    float* sA = dsm;
    float* sB = dsm + TILEF;

    const int tid = threadIdx.x;
    const int wid = tid >> 5;
    const int lane = tid & 31;
    const int g = lane >> 2;       // group row 0..7
    const int c = lane & 3;        // col-in-group 0..3
    const int block_row = blockIdx.x * 128;
    const int m0 = (wid >> 2) * 64;
    const int n0 = (wid & 3) * 32;

    float acc[4][4][4];
#pragma unroll
    for (int mt = 0; mt < 4; mt++)
#pragma unroll
        for (int nt = 0; nt < 4; nt++)
#pragma unroll
            for (int q = 0; q < 4; q++) acc[mt][nt][q] = 0.f;

    for (int c0 = 0; c0 < 128; c0 += 32) {
        const float* aptr = A + (size_t)block_row * DD + c0;
        const float* bptr = W + c0;

        if (c0) __syncthreads();
#pragma unroll
        for (int i = 0; i < 4; i++) {
            const int f = i * 256 + tid;          // 0..1023
            const int row = f >> 3;               // 0..127
            const int k4 = f & 7;
            const int so = k4 * 516 + row * 4;

            float4 va = make_float4(0.f, 0.f, 0.f, 0.f);
            if (block_row + row < n) va = *(const float4*)(aptr + (size_t)row * DD + k4 * 4);
            uint4 h;
            h.x = f32_to_tf32(va.x);
            h.y = f32_to_tf32(va.y);
            h.z = f32_to_tf32(va.z);
            h.w = f32_to_tf32(va.w);
            *(uint4*)(sA + so) = h;

            const float4 vb = *(const float4*)(bptr + (size_t)row * 128 + k4 * 4);
            h.x = f32_to_tf32(vb.x);
            h.y = f32_to_tf32(vb.y);
            h.z = f32_to_tf32(vb.z);
            h.w = f32_to_tf32(vb.w);
            *(uint4*)(sB + so) = h;
        }
        __syncthreads();

#pragma unroll
        for (int s = 0; s < 4; s++) {
            const int kA = 2 * s, kB = 2 * s + 1;
            uint32_t Ah[4][4], Bh[4][2];
#pragma unroll
            for (int mt = 0; mt < 4; mt++) {
                const int r0 = m0 + mt * 16 + g;
                const int i00 = kA * 516 + r0 * 4 + c;
                const int i10 = kB * 516 + r0 * 4 + c;
                Ah[mt][0] = __float_as_uint(sA[i00]);
                Ah[mt][1] = __float_as_uint(sA[i00 + 32]);
                Ah[mt][2] = __float_as_uint(sA[i10]);
                Ah[mt][3] = __float_as_uint(sA[i10 + 32]);
            }
#pragma unroll
            for (int nt = 0; nt < 4; nt++) {
                const int nn = n0 + nt * 8 + g;
                Bh[nt][0] = __float_as_uint(sB[kA * 516 + nn * 4 + c]);
                Bh[nt][1] = __float_as_uint(sB[kB * 516 + nn * 4 + c]);
            }
#pragma unroll
            for (int mt = 0; mt < 4; mt++)
#pragma unroll
                for (int nt = 0; nt < 4; nt++)
                    mma_tf32(acc[mt][nt], Ah[mt], Bh[nt]);
        }
    }

    // Epilogue
#pragma unroll
    for (int nt = 0; nt < 4; nt++) {
        const int col = n0 + nt * 8 + 2 * c;
        float b0v = 0.f, b1v = 0.f;
        if (!ADDPREV) {
            b0v = bn[col] + bs[col];
            b1v = bn[col + 1] + bs[col + 1];
        }
#pragma unroll
        for (int mt = 0; mt < 4; mt++) {
            const int r = block_row + m0 + mt * 16 + g;
            float v0 = acc[mt][nt][0] + b0v;
            float v1 = acc[mt][nt][1] + b1v;
            float v2 = acc[mt][nt][2] + b0v;
            float v3 = acc[mt][nt][3] + b1v;
            if (r < n) {
                float* p = out + (size_t)r * DD + col;
                if (ADDPREV) {
                    const float2 pv = *(const float2*)p;
                    v0 += pv.x; v1 += pv.y;
                }
                if (RELU) { v0 = fmaxf(v0, 0.f); v1 = fmaxf(v1, 0.f); }
                *(float2*)p = make_float2(v0, v1);
            }
            if (r + 8 < n) {
                float* p = out + (size_t)(r + 8) * DD + col;
                if (ADDPREV) {
                    const float2 pv = *(const float2*)p;
                    v2 += pv.x; v3 += pv.y;
                }
                if (RELU) { v2 = fmaxf(v2, 0.f); v3 = fmaxf(v3, 0.f); }
                *(float2*)p = make_float2(v2, v3);
            }
        }
    }
}

// ---------------------------------------------------------------------------
extern "C" void kernel_launch(void* const* d_in, const int* in_sizes, int n_in,
                              void* d_out, int out_size) {
    const float* x   = (const float*)d_in[0];
    const int* ei    = (const int*)d_in[1];
    const float* Wn1 = (const float*)d_in[2];
    const float* bn1 = (const float*)d_in[3];
    const float* Ws1 = (const float*)d_in[4];
    const float* bs1 = (const float*)d_in[5];
    const float* Wn2 = (const float*)d_in[6];
    const float* bn2 = (const float*)d_in[7];
    const float* Ws2 = (const float*)d_in[8];
    const float* bs2 = (const float*)d_in[9];
    float* out = (float*)d_out;

    const int n = in_sizes[0] / DD;
    const int E = in_sizes[1] / 2;
    const int* src = ei;
    const int* dst = ei + E;

    float* d_h1;    cudaGetSymbolAddress((void**)&d_h1, g_h1);
    float* d_agg;   cudaGetSymbolAddress((void**)&d_agg, g_agg);

    const int threads = 256;
    const int nb = (n + 1023) / 1024;
    const int gemm_blocks = (n + 127) / 128;
    const unsigned agg_blocks = ((unsigned)n * 32u + threads - 1) / threads;

    // Fork: side stream computes self-GEMMs concurrently with the LTS-bound
    // CSR build / aggregation on the main stream.
    cudaEventRecord(g_ev[0], 0);
    cudaStreamWaitEvent(g_s2, g_ev[0], 0);

    // s2: self1 = x @ Ws1^T + (bn1 + bs1)  -> h1
    gemm_half_kernel<false, false><<<gemm_blocks, 256, GEMM_SMEM, g_s2>>>(
        x, Ws1, bn1, bs1, d_h1, n);
    cudaEventRecord(g_ev[1], g_s2);

    // main: CSR build + agg1
    deg_kernel<<<(E + threads - 1) / threads, threads>>>(dst, E);
    scanA_kernel<<<nb, 1024>>>(n);
    scanB_kernel<<<1, 128>>>(nb);
    scanC_kernel<<<(n + 1 + threads - 1) / threads, threads>>>(n);
    fill_kernel<<<(E + threads - 1) / threads, threads>>>(src, dst, E);
    agg_kernel<<<agg_blocks, threads>>>(x, d_agg, n);

    // main: neigh1: h1 = relu(h1 + agg @ Wn1^T)   (needs self1)
    cudaStreamWaitEvent(0, g_ev[1], 0);
    gemm_half_kernel<true, true><<<gemm_blocks, 256, GEMM_SMEM>>>(
        d_agg, Wn1, nullptr, nullptr, d_h1, n);
    cudaEventRecord(g_ev[2], 0);

    // s2: self2 = h1 @ Ws2^T + (bn2 + bs2) -> out   (concurrent with agg2)
    cudaStreamWaitEvent(g_s2, g_ev[2], 0);
    gemm_half_kernel<false, false><<<gemm_blocks, 256, GEMM_SMEM, g_s2>>>(
        d_h1, Ws2, bn2, bs2, out, n);
    cudaEventRecord(g_ev[3], g_s2);

    // main: agg2 over h1
    agg_kernel<<<agg_blocks, threads>>>(d_h1, d_agg, n);

    // join + neigh2: out = out + agg @ Wn2^T
    cudaStreamWaitEvent(0, g_ev[3], 0);
    gemm_half_kernel<false, true><<<gemm_blocks, 256, GEMM_SMEM>>>(
        d_agg, Wn2, nullptr, nullptr, out, n);
}

// round 11
// speedup vs baseline: 1.6281x; 1.4168x over previous
#include <cuda_runtime.h>
#include <cuda_fp16.h>
#include <cstdint>

#define NN 100000
#define DD 128
#define EE_MAX 1700000

// Scratch (allocation-free rule: __device__ globals)
__device__ float g_agg[(size_t)NN * DD];
__device__ float g_h1[(size_t)NN * DD];
__device__ int   g_deg[NN];
__device__ int   g_cursor[NN];
__device__ int   g_rowptr[NN + 1];
__device__ int   g_col[EE_MAX];
__device__ int   g_partial[128];

// ---------------------------------------------------------------------------
__global__ void deg_kernel(const int* __restrict__ dst, int E) {
    int e = blockIdx.x * blockDim.x + threadIdx.x;
    if (e < E) atomicAdd(&g_deg[dst[e]], 1);
}

// Block-wise scan of g_deg -> g_rowptr (local exclusive) + raw block totals.
// Also re-zeros g_deg (next replay) and g_cursor (for fill).
__global__ __launch_bounds__(1024) void scanA_kernel(int n) {
    const int i = blockIdx.x * 1024 + threadIdx.x;
    const int lane = threadIdx.x & 31;
    const int w = threadIdx.x >> 5;
    const int v = (i < n) ? g_deg[i] : 0;
    int s = v;
#pragma unroll
    for (int o = 1; o < 32; o <<= 1) {
        int t = __shfl_up_sync(0xffffffffu, s, o);
        if (lane >= o) s += t;
    }
    __shared__ int wsum[32];
    if (lane == 31) wsum[w] = s;
    __syncthreads();
    if (w == 0) {
        int ws = wsum[lane];
#pragma unroll
        for (int o = 1; o < 32; o <<= 1) {
            int t = __shfl_up_sync(0xffffffffu, ws, o);
            if (lane >= o) ws += t;
        }
        wsum[lane] = ws;
    }
    __syncthreads();
    const int excl = s - v + (w ? wsum[w - 1] : 0);
    if (i < n) {
        g_rowptr[i] = excl;
        g_deg[i] = 0;
        g_cursor[i] = 0;
    }
    if (threadIdx.x == 1023) g_partial[blockIdx.x] = excl + v;   // block total
}

// Adds the prefix of block totals; each 256-block serves one 1024-region.
__global__ __launch_bounds__(256) void scanC_kernel(int n, int nb) {
    __shared__ int red[256];
    const int t = threadIdx.x;
    const int r = blockIdx.x >> 2;          // 1024-region index of this block
    red[t] = (t < r) ? g_partial[t] : 0;
    __syncthreads();
#pragma unroll
    for (int o = 128; o > 0; o >>= 1) {
        if (t < o) red[t] += red[t + o];
        __syncthreads();
    }
    const int S = red[0];
    const int i = blockIdx.x * 256 + t;
    if (i < n) g_rowptr[i] += S;
    if (i == n) {
        int tot = 0;
        for (int j = 0; j < nb; j++) tot += g_partial[j];
        g_rowptr[n] = tot;
    }
}

__global__ void fill_kernel(const int* __restrict__ src, const int* __restrict__ dst, int E) {
    int e = blockIdx.x * blockDim.x + threadIdx.x;
    if (e < E) {
        int d = dst[e];
        int p = atomicAdd(&g_cursor[d], 1);
        g_col[g_rowptr[d] + p] = src[e];
    }
}

// ---------------------------------------------------------------------------
// Gather-side mean aggregation: one warp per node, pre-normalized by 1/deg.
__global__ __launch_bounds__(256) void agg_kernel(const float* __restrict__ feat,
                                                  float* __restrict__ out, int n) {
    const int warp = (blockIdx.x * blockDim.x + threadIdx.x) >> 5;
    if (warp >= n) return;
    const int lane = threadIdx.x & 31;
    const int c = lane << 2;
    const int beg = g_rowptr[warp];
    const int end = g_rowptr[warp + 1];

    unsigned long long a01 = 0ull, a23 = 0ull;
    for (int base = beg; base < end; base += 32) {
        const int idx = base + lane;
        const int sv = (idx < end) ? g_col[idx] : 0;
        const int cnt = min(end - base, 32);
#pragma unroll 4
        for (int j = 0; j < cnt; j++) {
            const int s = __shfl_sync(0xffffffffu, sv, j);
            const ulonglong2 v = *(const ulonglong2*)(feat + (size_t)s * DD + c);
            asm("add.rn.f32x2 %0, %0, %1;" : "+l"(a01) : "l"(v.x));
            asm("add.rn.f32x2 %0, %0, %1;" : "+l"(a23) : "l"(v.y));
        }
    }
    const float inv = 1.0f / fmaxf((float)(end - beg), 1.0f);
    float4 r;
    asm("mov.b64 {%0, %1}, %2;" : "=f"(r.x), "=f"(r.y) : "l"(a01));
    asm("mov.b64 {%0, %1}, %2;" : "=f"(r.z), "=f"(r.w) : "l"(a23));
    r.x *= inv; r.y *= inv; r.z *= inv; r.w *= inv;
    *(float4*)(out + (size_t)warp * DD + c) = r;
}

// ---------------------------------------------------------------------------
// FP16 mma.sync (m16n8k16, fp32 accumulate) fused GEMM + bias(+relu).
// out[r][o] = relu?( sum_k<128 agg[r][k]*Wn[o][k] + sum_k A2[r][k]*Ws[o][k]
//                    + bn[o] + bs[o] )
// CTA: 128x128xK256, 8 warps (2m x 4n), warp tile 64x32, K chunks of 32.
// Operands converted fp32 -> fp16 during SMEM staging; fp32 accumulators.
// SMEM tile: [k2b (0..3)][row (0..127)][k2lo (0..3)] half2 words,
// row stride 4 words, k2b stride 520 words (pad keeps STS.128 conflict-free).
__device__ __forceinline__ uint32_t packh2(float a, float b) {
    __half2 h = __floats2half2_rn(a, b);
    return *(uint32_t*)&h;
}
__device__ __forceinline__ void mma_f16(float* d, const uint32_t* a, const uint32_t* b) {
    asm volatile(
        "mma.sync.aligned.m16n8k16.row.col.f32.f16.f16.f32 "
        "{%0,%1,%2,%3}, {%4,%5,%6,%7}, {%8,%9}, {%0,%1,%2,%3};"
        : "+f"(d[0]), "+f"(d[1]), "+f"(d[2]), "+f"(d[3])
        : "r"(a[0]), "r"(a[1]), "r"(a[2]), "r"(a[3]), "r"(b[0]), "r"(b[1]));
}

template <bool RELU>
__global__ __launch_bounds__(256) void gemm_kernel(
    const float* __restrict__ A2, const float* __restrict__ Wn,
    const float* __restrict__ Ws, const float* __restrict__ bn,
    const float* __restrict__ bs, float* __restrict__ out, int n) {
    __shared__ uint32_t sA[4 * 520];
    __shared__ uint32_t sB[4 * 520];

    const int tid = threadIdx.x;
    const int wid = tid >> 5;
    const int lane = tid & 31;
    const int g = lane >> 2;       // group row 0..7
    const int c = lane & 3;        // col-in-group 0..3
    const int block_row = blockIdx.x * 128;
    const int m0 = (wid >> 2) * 64;
    const int n0 = (wid & 3) * 32;

    float acc[4][4][4];
#pragma unroll
    for (int mt = 0; mt < 4; mt++)
#pragma unroll
        for (int nt = 0; nt < 4; nt++)
#pragma unroll
            for (int q = 0; q < 4; q++) acc[mt][nt][q] = 0.f;

    for (int c0 = 0; c0 < 256; c0 += 32) {
        const float* aptr = (c0 < 128) ? g_agg + (size_t)block_row * DD + c0
                                       : A2 + (size_t)block_row * DD + (c0 - 128);
        const float* bptr = (c0 < 128) ? (Wn + c0) : (Ws + (c0 - 128));

        if (c0) __syncthreads();
        // Stage A and B: each thread handles 2 slots of 8 k-values (2 float4s)
#pragma unroll
        for (int i = 0; i < 2; i++) {
            const int s2 = i * 256 + tid;     // 0..511
            const int row = s2 >> 2;          // 0..127
            const int k2b = s2 & 3;           // 8-k block within chunk
            const int so = k2b * 520 + row * 4;

            float4 v0 = make_float4(0.f, 0.f, 0.f, 0.f), v1 = v0;
            if (block_row + row < n) {
                const float4* p = (const float4*)(aptr + (size_t)row * DD + k2b * 8);
                v0 = p[0]; v1 = p[1];
            }
            uint4 h;
            h.x = packh2(v0.x, v0.y); h.y = packh2(v0.z, v0.w);
            h.z = packh2(v1.x, v1.y); h.w = packh2(v1.z, v1.w);
            *(uint4*)(sA + so) = h;

            const float4* q = (const float4*)(bptr + (size_t)row * 128 + k2b * 8);
            const float4 w0 = q[0], w1 = q[1];
            h.x = packh2(w0.x, w0.y); h.y = packh2(w0.z, w0.w);
            h.z = packh2(w1.x, w1.y); h.w = packh2(w1.z, w1.w);
            *(uint4*)(sB + so) = h;
        }
        __syncthreads();

#pragma unroll
        for (int st = 0; st < 2; st++) {      // two k16 steps per 32-chunk
            const int kb0 = st * 2 * 520;
            const int kb1 = kb0 + 520;
            uint32_t Ar[4][4], Br[4][2];
#pragma unroll
            for (int mt = 0; mt < 4; mt++) {
                const int r0 = (m0 + mt * 16 + g) * 4 + c;
                Ar[mt][0] = sA[kb0 + r0];
                Ar[mt][1] = sA[kb0 + r0 + 32];   // row +8
                Ar[mt][2] = sA[kb1 + r0];
                Ar[mt][3] = sA[kb1 + r0 + 32];
            }
#pragma unroll
            for (int nt = 0; nt < 4; nt++) {
                const int nn = (n0 + nt * 8 + g) * 4 + c;
                Br[nt][0] = sB[kb0 + nn];
                Br[nt][1] = sB[kb1 + nn];
            }
#pragma unroll
            for (int mt = 0; mt < 4; mt++)
#pragma unroll
                for (int nt = 0; nt < 4; nt++)
                    mma_f16(acc[mt][nt], Ar[mt], Br[nt]);
        }
    }

    // Epilogue: bias + optional relu, float2 stores
#pragma unroll
    for (int nt = 0; nt < 4; nt++) {
        const int col = n0 + nt * 8 + 2 * c;
        const float b0v = bn[col] + bs[col];
        const float b1v = bn[col + 1] + bs[col + 1];
#pragma unroll
        for (int mt = 0; mt < 4; mt++) {
            const int r = block_row + m0 + mt * 16 + g;
            float v0 = acc[mt][nt][0] + b0v;
            float v1 = acc[mt][nt][1] + b1v;
            float v2 = acc[mt][nt][2] + b0v;
            float v3 = acc[mt][nt][3] + b1v;
            if (RELU) {
                v0 = fmaxf(v0, 0.f); v1 = fmaxf(v1, 0.f);
                v2 = fmaxf(v2, 0.f); v3 = fmaxf(v3, 0.f);
            }
            if (r < n)     *(float2*)(out + (size_t)r * DD + col) = make_float2(v0, v1);
            if (r + 8 < n) *(float2*)(out + (size_t)(r + 8) * DD + col) = make_float2(v2, v3);
        }
    }
}

// ---------------------------------------------------------------------------
extern "C" void kernel_launch(void* const* d_in, const int* in_sizes, int n_in,
                              void* d_out, int out_size) {
    const float* x   = (const float*)d_in[0];
    const int* ei    = (const int*)d_in[1];
    const float* Wn1 = (const float*)d_in[2];
    const float* bn1 = (const float*)d_in[3];
    const float* Ws1 = (const float*)d_in[4];
    const float* bs1 = (const float*)d_in[5];
    const float* Wn2 = (const float*)d_in[6];
    const float* bn2 = (const float*)d_in[7];
    const float* Ws2 = (const float*)d_in[8];
    const float* bs2 = (const float*)d_in[9];
    float* out = (float*)d_out;

    const int n = in_sizes[0] / DD;
    const int E = in_sizes[1] / 2;
    const int* src = ei;
    const int* dst = ei + E;

    float* d_h1;    cudaGetSymbolAddress((void**)&d_h1, g_h1);
    float* d_agg;   cudaGetSymbolAddress((void**)&d_agg, g_agg);

    const int threads = 256;
    const int nb = (n + 1023) / 1024;

    // --- CSR build (deg/cursor re-zeroed inside scanA for replay) ---
    deg_kernel<<<(E + threads - 1) / threads, threads>>>(dst, E);
    scanA_kernel<<<nb, 1024>>>(n);
    scanC_kernel<<<(n + 1 + threads - 1) / threads, threads>>>(n, nb);
    fill_kernel<<<(E + threads - 1) / threads, threads>>>(src, dst, E);

    const unsigned agg_blocks = ((unsigned)n * 32u + threads - 1) / threads;
    const int gemm_blocks = (n + 127) / 128;

    // layer 1: mean-aggregate x -> agg, fp16-MMA GEMM + bias + relu -> h1
    agg_kernel<<<agg_blocks, threads>>>(x, d_agg, n);
    gemm_kernel<true><<<gemm_blocks, 256>>>(x, Wn1, Ws1, bn1, bs1, d_h1, n);

    // layer 2: mean-aggregate h1 -> agg, fp16-MMA GEMM + bias -> out
    agg_kernel<<<agg_blocks, threads>>>(d_h1, d_agg, n);
    gemm_kernel<false><<<gemm_blocks, 256>>>(d_h1, Wn2, Ws2, bn2, bs2, out, n);
}

// round 12
// speedup vs baseline: 1.8726x; 1.1501x over previous
#include <cuda_runtime.h>
#include <cuda_fp16.h>
#include <cstdint>

#define NN 100000
#define DD 128
#define EE_MAX 1700000

// Scratch (allocation-free rule: __device__ globals)
__device__ __half g_xh[(size_t)NN * DD];     // fp16 copy of x
__device__ __half g_h1h[(size_t)NN * DD];    // fp16 h1 (only copy)
__device__ __half g_aggh[(size_t)NN * DD];   // fp16 aggregated means
__device__ int   g_deg[NN];
__device__ int   g_cursor[NN];
__device__ int   g_rowptr[NN + 1];
__device__ int   g_col[EE_MAX];
__device__ int   g_partial[128];

// ---------------------------------------------------------------------------
__global__ void cvt_h_kernel(const float* __restrict__ in,
                             __half* __restrict__ out, int n8) {
    int i = blockIdx.x * blockDim.x + threadIdx.x;
    if (i < n8) {
        const float4* p = (const float4*)in + i * 2;
        const float4 v0 = p[0], v1 = p[1];
        uint4 o;
        __half2 h;
        h = __floats2half2_rn(v0.x, v0.y); o.x = *(uint32_t*)&h;
        h = __floats2half2_rn(v0.z, v0.w); o.y = *(uint32_t*)&h;
        h = __floats2half2_rn(v1.x, v1.y); o.z = *(uint32_t*)&h;
        h = __floats2half2_rn(v1.z, v1.w); o.w = *(uint32_t*)&h;
        ((uint4*)out)[i] = o;
    }
}

__global__ void deg_kernel(const int* __restrict__ dst, int E) {
    int e = blockIdx.x * blockDim.x + threadIdx.x;
    if (e < E) atomicAdd(&g_deg[dst[e]], 1);
}

// Block-wise scan of g_deg -> g_rowptr (local exclusive) + block totals.
// Also re-zeros g_deg (next replay) and g_cursor (for fill).
__global__ __launch_bounds__(1024) void scanA_kernel(int n) {
    const int i = blockIdx.x * 1024 + threadIdx.x;
    const int lane = threadIdx.x & 31;
    const int w = threadIdx.x >> 5;
    const int v = (i < n) ? g_deg[i] : 0;
    int s = v;
#pragma unroll
    for (int o = 1; o < 32; o <<= 1) {
        int t = __shfl_up_sync(0xffffffffu, s, o);
        if (lane >= o) s += t;
    }
    __shared__ int wsum[32];
    if (lane == 31) wsum[w] = s;
    __syncthreads();
    if (w == 0) {
        int ws = wsum[lane];
#pragma unroll
        for (int o = 1; o < 32; o <<= 1) {
            int t = __shfl_up_sync(0xffffffffu, ws, o);
            if (lane >= o) ws += t;
        }
        wsum[lane] = ws;
    }
    __syncthreads();
    const int excl = s - v + (w ? wsum[w - 1] : 0);
    if (i < n) {
        g_rowptr[i] = excl;
        g_deg[i] = 0;
        g_cursor[i] = 0;
    }
    if (threadIdx.x == 1023) g_partial[blockIdx.x] = excl + v;
}

// Adds the prefix of block totals; each 256-block serves one 1024-region.
__global__ __launch_bounds__(256) void scanC_kernel(int n, int nb) {
    __shared__ int red[256];
    const int t = threadIdx.x;
    const int r = blockIdx.x >> 2;
    red[t] = (t < r) ? g_partial[t] : 0;
    __syncthreads();
#pragma unroll
    for (int o = 128; o > 0; o >>= 1) {
        if (t < o) red[t] += red[t + o];
        __syncthreads();
    }
    const int S = red[0];
    const int i = blockIdx.x * 256 + t;
    if (i < n) g_rowptr[i] += S;
    if (i == n) {
        int tot = 0;
        for (int j = 0; j < nb; j++) tot += g_partial[j];
        g_rowptr[n] = tot;
    }
}

__global__ void fill_kernel(const int* __restrict__ src, const int* __restrict__ dst, int E) {
    int e = blockIdx.x * blockDim.x + threadIdx.x;
    if (e < E) {
        int d = dst[e];
        int p = atomicAdd(&g_cursor[d], 1);
        g_col[g_rowptr[d] + p] = src[e];
    }
}

// ---------------------------------------------------------------------------
// Gather-side mean aggregation over fp16 features: one warp per node.
// fp32 accumulation; fp16 output (pre-normalized by 1/deg).
__global__ __launch_bounds__(256) void agg_kernel(const __half* __restrict__ feat,
                                                  __half* __restrict__ out, int n) {
    const int warp = (blockIdx.x * blockDim.x + threadIdx.x) >> 5;
    if (warp >= n) return;
    const int lane = threadIdx.x & 31;
    const int c = lane << 2;
    const int beg = g_rowptr[warp];
    const int end = g_rowptr[warp + 1];

    float a0 = 0.f, a1 = 0.f, a2 = 0.f, a3 = 0.f;
    for (int base = beg; base < end; base += 32) {
        const int idx = base + lane;
        const int sv = (idx < end) ? g_col[idx] : 0;
        const int cnt = min(end - base, 32);
#pragma unroll 4
        for (int j = 0; j < cnt; j++) {
            const int s = __shfl_sync(0xffffffffu, sv, j);
            const uint2 u = *(const uint2*)(feat + (size_t)s * DD + c);
            const float2 p0 = __half22float2(*(const __half2*)&u.x);
            const float2 p1 = __half22float2(*(const __half2*)&u.y);
            a0 += p0.x; a1 += p0.y; a2 += p1.x; a3 += p1.y;
        }
    }
    const float inv = 1.0f / fmaxf((float)(end - beg), 1.0f);
    __half2 h0 = __floats2half2_rn(a0 * inv, a1 * inv);
    __half2 h1 = __floats2half2_rn(a2 * inv, a3 * inv);
    uint2 o;
    o.x = *(uint32_t*)&h0;
    o.y = *(uint32_t*)&h1;
    *(uint2*)(out + (size_t)warp * DD + c) = o;
}

// ---------------------------------------------------------------------------
// FP16 mma.sync (m16n8k16, fp32 accumulate) fused GEMM + bias(+relu).
// out[r][o] = relu?( A1[r][:] @ Wn[o][:] + A2[r][:] @ Ws[o][:] + bn[o]+bs[o] )
// A1/A2 are fp16 (staged as raw copies); W fp32 (cvt at staging).
// OUTHALF: write fp16 (h1 path). Otherwise fp32 (final output).
// SMEM tile: [k2b (0..3)][row (0..127)][k2lo (0..3)] half2 words, k2b stride 520.
__device__ __forceinline__ uint32_t packh2(float a, float b) {
    __half2 h = __floats2half2_rn(a, b);
    return *(uint32_t*)&h;
}
__device__ __forceinline__ void mma_f16(float* d, const uint32_t* a, const uint32_t* b) {
    asm volatile(
        "mma.sync.aligned.m16n8k16.row.col.f32.f16.f16.f32 "
        "{%0,%1,%2,%3}, {%4,%5,%6,%7}, {%8,%9}, {%0,%1,%2,%3};"
        : "+f"(d[0]), "+f"(d[1]), "+f"(d[2]), "+f"(d[3])
        : "r"(a[0]), "r"(a[1]), "r"(a[2]), "r"(a[3]), "r"(b[0]), "r"(b[1]));
}

template <bool RELU, bool OUTHALF>
__global__ __launch_bounds__(256) void gemm_kernel(
    const __half* __restrict__ A1, const __half* __restrict__ A2,
    const float* __restrict__ Wn, const float* __restrict__ Ws,
    const float* __restrict__ bn, const float* __restrict__ bs,
    float* __restrict__ outf, __half* __restrict__ outh, int n) {
    __shared__ uint32_t sA[4 * 520];
    __shared__ uint32_t sB[4 * 520];

    const int tid = threadIdx.x;
    const int wid = tid >> 5;
    const int lane = tid & 31;
    const int g = lane >> 2;
    const int c = lane & 3;
    const int block_row = blockIdx.x * 128;
    const int m0 = (wid >> 2) * 64;
    const int n0 = (wid & 3) * 32;

    float acc[4][4][4];
#pragma unroll
    for (int mt = 0; mt < 4; mt++)
#pragma unroll
        for (int nt = 0; nt < 4; nt++)
#pragma unroll
            for (int q = 0; q < 4; q++) acc[mt][nt][q] = 0.f;

    for (int c0 = 0; c0 < 256; c0 += 32) {
        const __half* aptr = (c0 < 128)
            ? (A1 + (size_t)block_row * DD + c0)
            : (A2 + (size_t)block_row * DD + (c0 - 128));
        const float* bptr = (c0 < 128) ? (Wn + c0) : (Ws + (c0 - 128));

        if (c0) __syncthreads();
#pragma unroll
        for (int i = 0; i < 2; i++) {
            const int s2 = i * 256 + tid;     // 0..511
            const int row = s2 >> 2;          // 0..127
            const int k2b = s2 & 3;           // 8-k block within chunk
            const int so = k2b * 520 + row * 4;

            uint4 h = make_uint4(0u, 0u, 0u, 0u);
            if (block_row + row < n)
                h = *(const uint4*)(aptr + (size_t)row * DD + k2b * 8);
            *(uint4*)(sA + so) = h;

            const float4* q = (const float4*)(bptr + (size_t)row * 128 + k2b * 8);
            const float4 w0 = q[0], w1 = q[1];
            h.x = packh2(w0.x, w0.y); h.y = packh2(w0.z, w0.w);
            h.z = packh2(w1.x, w1.y); h.w = packh2(w1.z, w1.w);
            *(uint4*)(sB + so) = h;
        }
        __syncthreads();

#pragma unroll
        for (int st = 0; st < 2; st++) {      // two k16 steps per 32-chunk
            const int kb0 = st * 2 * 520;
            const int kb1 = kb0 + 520;
            uint32_t Ar[4][4], Br[4][2];
#pragma unroll
            for (int mt = 0; mt < 4; mt++) {
                const int r0 = (m0 + mt * 16 + g) * 4 + c;
                Ar[mt][0] = sA[kb0 + r0];
                Ar[mt][1] = sA[kb0 + r0 + 32];
                Ar[mt][2] = sA[kb1 + r0];
                Ar[mt][3] = sA[kb1 + r0 + 32];
            }
#pragma unroll
            for (int nt = 0; nt < 4; nt++) {
                const int nn = (n0 + nt * 8 + g) * 4 + c;
                Br[nt][0] = sB[kb0 + nn];
                Br[nt][1] = sB[kb1 + nn];
            }
#pragma unroll
            for (int mt = 0; mt < 4; mt++)
#pragma unroll
                for (int nt = 0; nt < 4; nt++)
                    mma_f16(acc[mt][nt], Ar[mt], Br[nt]);
        }
    }

    // Epilogue: bias + optional relu
#pragma unroll
    for (int nt = 0; nt < 4; nt++) {
        const int col = n0 + nt * 8 + 2 * c;
        const float b0v = bn[col] + bs[col];
        const float b1v = bn[col + 1] + bs[col + 1];
#pragma unroll
        for (int mt = 0; mt < 4; mt++) {
            const int r = block_row + m0 + mt * 16 + g;
            float v0 = acc[mt][nt][0] + b0v;
            float v1 = acc[mt][nt][1] + b1v;
            float v2 = acc[mt][nt][2] + b0v;
            float v3 = acc[mt][nt][3] + b1v;
            if (RELU) {
                v0 = fmaxf(v0, 0.f); v1 = fmaxf(v1, 0.f);
                v2 = fmaxf(v2, 0.f); v3 = fmaxf(v3, 0.f);
            }
            if (r < n) {
                if (OUTHALF) {
                    *(uint32_t*)(outh + (size_t)r * DD + col) = packh2(v0, v1);
                } else {
                    *(float2*)(outf + (size_t)r * DD + col) = make_float2(v0, v1);
                }
            }
            if (r + 8 < n) {
                if (OUTHALF) {
                    *(uint32_t*)(outh + (size_t)(r + 8) * DD + col) = packh2(v2, v3);
                } else {
                    *(float2*)(outf + (size_t)(r + 8) * DD + col) = make_float2(v2, v3);
                }
            }
        }
    }
}

// ---------------------------------------------------------------------------
extern "C" void kernel_launch(void* const* d_in, const int* in_sizes, int n_in,
                              void* d_out, int out_size) {
    const float* x   = (const float*)d_in[0];
    const int* ei    = (const int*)d_in[1];
    const float* Wn1 = (const float*)d_in[2];
    const float* bn1 = (const float*)d_in[3];
    const float* Ws1 = (const float*)d_in[4];
    const float* bs1 = (const float*)d_in[5];
    const float* Wn2 = (const float*)d_in[6];
    const float* bn2 = (const float*)d_in[7];
    const float* Ws2 = (const float*)d_in[8];
    const float* bs2 = (const float*)d_in[9];
    float* out = (float*)d_out;

    const int n = in_sizes[0] / DD;
    const int E = in_sizes[1] / 2;
    const int* src = ei;
    const int* dst = ei + E;

    __half* d_xh;   cudaGetSymbolAddress((void**)&d_xh, g_xh);
    __half* d_h1h;  cudaGetSymbolAddress((void**)&d_h1h, g_h1h);
    __half* d_aggh; cudaGetSymbolAddress((void**)&d_aggh, g_aggh);

    const int threads = 256;
    const int nb = (n + 1023) / 1024;
    const int n8 = (n * DD) / 8;

    // --- feature cache + CSR build ---
    cvt_h_kernel<<<(n8 + threads - 1) / threads, threads>>>(x, d_xh, n8);
    deg_kernel<<<(E + threads - 1) / threads, threads>>>(dst, E);
    scanA_kernel<<<nb, 1024>>>(n);
    scanC_kernel<<<(n + 1 + threads - 1) / threads, threads>>>(n, nb);
    fill_kernel<<<(E + threads - 1) / threads, threads>>>(src, dst, E);

    const unsigned agg_blocks = ((unsigned)n * 32u + threads - 1) / threads;
    const int gemm_blocks = (n + 127) / 128;

    // layer 1: mean-aggregate x_h -> agg_h, GEMM + bias + relu -> h1 (fp16)
    agg_kernel<<<agg_blocks, threads>>>(d_xh, d_aggh, n);
    gemm_kernel<true, true><<<gemm_blocks, 256>>>(
        d_aggh, d_xh, Wn1, Ws1, bn1, bs1, nullptr, d_h1h, n);

    // layer 2: mean-aggregate h1_h -> agg_h, GEMM + bias -> out (fp32)
    agg_kernel<<<agg_blocks, threads>>>(d_h1h, d_aggh, n);
    gemm_kernel<false, false><<<gemm_blocks, 256>>>(
        d_aggh, d_h1h, Wn2, Ws2, bn2, bs2, out, nullptr, n);
}

// round 13
// speedup vs baseline: 1.8843x; 1.0063x over previous
#include <cuda_runtime.h>
#include <cuda_fp16.h>
#include <cstdint>

#define NN 100000
#define DD 128
#define EE_MAX 1700000

// Scratch (allocation-free rule: __device__ globals)
__device__ __half g_xh[(size_t)NN * DD];     // fp16 copy of x
__device__ __half g_h1h[(size_t)NN * DD];    // fp16 h1 (only copy)
__device__ __half g_aggh[(size_t)NN * DD];   // fp16 aggregated means
__device__ __half g_wh[4 * 128 * 128];       // fp16 weights: Wn1,Ws1,Wn2,Ws2
__device__ float g_bsum[2][DD];              // bn+bs per layer
__device__ int   g_deg[NN];
__device__ int   g_cursor[NN];
__device__ int   g_rowptr[NN + 1];
__device__ int   g_col[EE_MAX];
__device__ int   g_partial[128];

// ---------------------------------------------------------------------------
__device__ __forceinline__ uint32_t packh2(float a, float b) {
    __half2 h = __floats2half2_rn(a, b);
    return *(uint32_t*)&h;
}

// Heterogeneous prep: deg histogram | x->fp16 | weights->fp16 + bias sums.
__global__ __launch_bounds__(256) void prep_kernel(
    const float* __restrict__ x, const int* __restrict__ dst, int E, int n8,
    const float* __restrict__ Wn1, const float* __restrict__ Ws1,
    const float* __restrict__ Wn2, const float* __restrict__ Ws2,
    const float* __restrict__ bn1, const float* __restrict__ bs1,
    const float* __restrict__ bn2, const float* __restrict__ bs2,
    int nbDeg, int nbCvt) {
    const int b = blockIdx.x;
    if (b < nbDeg) {
        const int e = b * 256 + threadIdx.x;
        if (e < E) atomicAdd(&g_deg[dst[e]], 1);
    } else if (b < nbDeg + nbCvt) {
        const int i = (b - nbDeg) * 256 + threadIdx.x;
        if (i < n8) {
            const float4* p = (const float4*)x + i * 2;
            const float4 v0 = p[0], v1 = p[1];
            uint4 o;
            o.x = packh2(v0.x, v0.y);
            o.y = packh2(v0.z, v0.w);
            o.z = packh2(v1.x, v1.y);
            o.w = packh2(v1.z, v1.w);
            ((uint4*)g_xh)[i] = o;
        }
    } else {
        const int bw = b - nbDeg - nbCvt;            // 0..7
        const int t0 = bw * 256 + threadIdx.x;       // 0..2047
#pragma unroll 1
        for (int i = t0; i < 8192; i += 2048) {      // 8192 uint4 = 65536 halves
            const int m = i >> 11;                   // matrix 0..3
            const int r = i & 2047;                  // uint4 index in matrix
            const float* W = (m == 0) ? Wn1 : (m == 1) ? Ws1 : (m == 2) ? Wn2 : Ws2;
            const float4* p = (const float4*)W + r * 2;
            const float4 v0 = p[0], v1 = p[1];
            uint4 o;
            o.x = packh2(v0.x, v0.y);
            o.y = packh2(v0.z, v0.w);
            o.z = packh2(v1.x, v1.y);
            o.w = packh2(v1.z, v1.w);
            ((uint4*)g_wh)[i] = o;
        }
        if (bw == 0 && threadIdx.x < 128) {
            g_bsum[0][threadIdx.x] = bn1[threadIdx.x] + bs1[threadIdx.x];
            g_bsum[1][threadIdx.x] = bn2[threadIdx.x] + bs2[threadIdx.x];
        }
    }
}

// Block-wise scan of g_deg -> g_rowptr (local exclusive) + block totals.
// Also re-zeros g_deg (next replay) and g_cursor (for fill).
__global__ __launch_bounds__(1024) void scanA_kernel(int n) {
    const int i = blockIdx.x * 1024 + threadIdx.x;
    const int lane = threadIdx.x & 31;
    const int w = threadIdx.x >> 5;
    const int v = (i < n) ? g_deg[i] : 0;
    int s = v;
#pragma unroll
    for (int o = 1; o < 32; o <<= 1) {
        int t = __shfl_up_sync(0xffffffffu, s, o);
        if (lane >= o) s += t;
    }
    __shared__ int wsum[32];
    if (lane == 31) wsum[w] = s;
    __syncthreads();
    if (w == 0) {
        int ws = wsum[lane];
#pragma unroll
        for (int o = 1; o < 32; o <<= 1) {
            int t = __shfl_up_sync(0xffffffffu, ws, o);
            if (lane >= o) ws += t;
        }
        wsum[lane] = ws;
    }
    __syncthreads();
    const int excl = s - v + (w ? wsum[w - 1] : 0);
    if (i < n) {
        g_rowptr[i] = excl;
        g_deg[i] = 0;
        g_cursor[i] = 0;
    }
    if (threadIdx.x == 1023) g_partial[blockIdx.x] = excl + v;
}

// Adds the prefix of block totals; each 256-block serves one 1024-region.
__global__ __launch_bounds__(256) void scanC_kernel(int n, int nb) {
    __shared__ int red[256];
    const int t = threadIdx.x;
    const int r = blockIdx.x >> 2;
    red[t] = (t < r) ? g_partial[t] : 0;
    __syncthreads();
#pragma unroll
    for (int o = 128; o > 0; o >>= 1) {
        if (t < o) red[t] += red[t + o];
        __syncthreads();
    }
    const int S = red[0];
    const int i = blockIdx.x * 256 + t;
    if (i < n) g_rowptr[i] += S;
    if (i == n) {
        int tot = 0;
        for (int j = 0; j < nb; j++) tot += g_partial[j];
        g_rowptr[n] = tot;
    }
}

__global__ void fill_kernel(const int* __restrict__ src, const int* __restrict__ dst, int E) {
    int e = blockIdx.x * blockDim.x + threadIdx.x;
    if (e < E) {
        int d = dst[e];
        int p = atomicAdd(&g_cursor[d], 1);
        g_col[g_rowptr[d] + p] = src[e];
    }
}

// ---------------------------------------------------------------------------
// Paired-neighbor mean aggregation over fp16 features: one warp per node.
// The two warp halves process two neighbors at once: lanes 0-15 handle
// neighbor j, lanes 16-31 neighbor j+1 (per-lane shfl source). Each lane
// loads uint4 (8 halves = 16B); 16 lanes cover the 256B row. fp32 accum;
// cross-half reduction via shfl; fp16 output pre-normalized by 1/deg.
__global__ __launch_bounds__(256) void agg_kernel(const __half* __restrict__ feat,
                                                  __half* __restrict__ out, int n) {
    const int warp = (blockIdx.x * blockDim.x + threadIdx.x) >> 5;
    if (warp >= n) return;
    const int lane = threadIdx.x & 31;
    const int half = lane >> 4;
    const int l16 = lane & 15;
    const int c = l16 << 3;            // 8 halves per lane
    const int beg = g_rowptr[warp];
    const int end = g_rowptr[warp + 1];

    float a0 = 0.f, a1 = 0.f, a2 = 0.f, a3 = 0.f;
    float a4 = 0.f, a5 = 0.f, a6 = 0.f, a7 = 0.f;
    for (int base = beg; base < end; base += 32) {
        const int idx = base + lane;
        const int sv = (idx < end) ? g_col[idx] : 0;
        const int cnt = min(end - base, 32);
#pragma unroll 4
        for (int j = 0; j < cnt; j += 2) {
            const int jj = j + half;
            const int s = __shfl_sync(0xffffffffu, sv, jj);
            if (jj < cnt) {
                const uint4 u = *(const uint4*)(feat + (size_t)s * DD + c);
                float2 p;
                p = __half22float2(*(const __half2*)&u.x); a0 += p.x; a1 += p.y;
                p = __half22float2(*(const __half2*)&u.y); a2 += p.x; a3 += p.y;
                p = __half22float2(*(const __half2*)&u.z); a4 += p.x; a5 += p.y;
                p = __half22float2(*(const __half2*)&u.w); a6 += p.x; a7 += p.y;
            }
        }
    }
    // combine halves: lanes 0-15 pick up lanes 16-31's partials
    a0 += __shfl_down_sync(0xffffffffu, a0, 16);
    a1 += __shfl_down_sync(0xffffffffu, a1, 16);
    a2 += __shfl_down_sync(0xffffffffu, a2, 16);
    a3 += __shfl_down_sync(0xffffffffu, a3, 16);
    a4 += __shfl_down_sync(0xffffffffu, a4, 16);
    a5 += __shfl_down_sync(0xffffffffu, a5, 16);
    a6 += __shfl_down_sync(0xffffffffu, a6, 16);
    a7 += __shfl_down_sync(0xffffffffu, a7, 16);
    if (half == 0) {
        const float inv = 1.0f / fmaxf((float)(end - beg), 1.0f);
        uint4 o;
        o.x = packh2(a0 * inv, a1 * inv);
        o.y = packh2(a2 * inv, a3 * inv);
        o.z = packh2(a4 * inv, a5 * inv);
        o.w = packh2(a6 * inv, a7 * inv);
        *(uint4*)(out + (size_t)warp * DD + c) = o;
    }
}

// ---------------------------------------------------------------------------
// FP16 mma.sync (m16n8k16, fp32 accumulate) fused GEMM + bias(+relu).
// out[r][o] = relu?( A1[r][:] @ Wn[o][:] + A2[r][:] @ Ws[o][:] + bsum[o] )
// A and W both fp16 in global; staging is raw uint4 copies.
// SMEM tile: [k2b (0..3)][row (0..127)][k2lo (0..3)] half2 words, k2b stride 520.
__device__ __forceinline__ void mma_f16(float* d, const uint32_t* a, const uint32_t* b) {
    asm volatile(
        "mma.sync.aligned.m16n8k16.row.col.f32.f16.f16.f32 "
        "{%0,%1,%2,%3}, {%4,%5,%6,%7}, {%8,%9}, {%0,%1,%2,%3};"
        : "+f"(d[0]), "+f"(d[1]), "+f"(d[2]), "+f"(d[3])
        : "r"(a[0]), "r"(a[1]), "r"(a[2]), "r"(a[3]), "r"(b[0]), "r"(b[1]));
}

template <bool RELU, bool OUTHALF>
__global__ __launch_bounds__(256) void gemm_kernel(
    const __half* __restrict__ A1, const __half* __restrict__ A2,
    const __half* __restrict__ Wnh, const __half* __restrict__ Wsh,
    const float* __restrict__ bsum,
    float* __restrict__ outf, __half* __restrict__ outh, int n) {
    __shared__ uint32_t sA[4 * 520];
    __shared__ uint32_t sB[4 * 520];

    const int tid = threadIdx.x;
    const int wid = tid >> 5;
    const int lane = tid & 31;
    const int g = lane >> 2;
    const int c = lane & 3;
    const int block_row = blockIdx.x * 128;
    const int m0 = (wid >> 2) * 64;
    const int n0 = (wid & 3) * 32;

    float acc[4][4][4];
#pragma unroll
    for (int mt = 0; mt < 4; mt++)
#pragma unroll
        for (int nt = 0; nt < 4; nt++)
#pragma unroll
            for (int q = 0; q < 4; q++) acc[mt][nt][q] = 0.f;

    for (int c0 = 0; c0 < 256; c0 += 32) {
        const __half* aptr = (c0 < 128)
            ? (A1 + (size_t)block_row * DD + c0)
            : (A2 + (size_t)block_row * DD + (c0 - 128));
        const __half* bptr = (c0 < 128) ? (Wnh + c0) : (Wsh + (c0 - 128));

        if (c0) __syncthreads();
#pragma unroll
        for (int i = 0; i < 2; i++) {
            const int s2 = i * 256 + tid;     // 0..511
            const int row = s2 >> 2;          // 0..127
            const int k2b = s2 & 3;           // 8-k block within chunk
            const int so = k2b * 520 + row * 4;

            uint4 h = make_uint4(0u, 0u, 0u, 0u);
            if (block_row + row < n)
                h = *(const uint4*)(aptr + (size_t)row * DD + k2b * 8);
            *(uint4*)(sA + so) = h;

            const uint4 w = *(const uint4*)(bptr + (size_t)row * 128 + k2b * 8);
            *(uint4*)(sB + so) = w;
        }
        __syncthreads();

#pragma unroll
        for (int st = 0; st < 2; st++) {      // two k16 steps per 32-chunk
            const int kb0 = st * 2 * 520;
            const int kb1 = kb0 + 520;
            uint32_t Ar[4][4], Br[4][2];
#pragma unroll
            for (int mt = 0; mt < 4; mt++) {
                const int r0 = (m0 + mt * 16 + g) * 4 + c;
                Ar[mt][0] = sA[kb0 + r0];
                Ar[mt][1] = sA[kb0 + r0 + 32];
                Ar[mt][2] = sA[kb1 + r0];
                Ar[mt][3] = sA[kb1 + r0 + 32];
            }
#pragma unroll
            for (int nt = 0; nt < 4; nt++) {
                const int nn = (n0 + nt * 8 + g) * 4 + c;
                Br[nt][0] = sB[kb0 + nn];
                Br[nt][1] = sB[kb1 + nn];
            }
#pragma unroll
            for (int mt = 0; mt < 4; mt++)
#pragma unroll
                for (int nt = 0; nt < 4; nt++)
                    mma_f16(acc[mt][nt], Ar[mt], Br[nt]);
        }
    }

    // Epilogue: bias + optional relu
#pragma unroll
    for (int nt = 0; nt < 4; nt++) {
        const int col = n0 + nt * 8 + 2 * c;
        const float b0v = bsum[col];
        const float b1v = bsum[col + 1];
#pragma unroll
        for (int mt = 0; mt < 4; mt++) {
            const int r = block_row + m0 + mt * 16 + g;
            float v0 = acc[mt][nt][0] + b0v;
            float v1 = acc[mt][nt][1] + b1v;
            float v2 = acc[mt][nt][2] + b0v;
            float v3 = acc[mt][nt][3] + b1v;
            if (RELU) {
                v0 = fmaxf(v0, 0.f); v1 = fmaxf(v1, 0.f);
                v2 = fmaxf(v2, 0.f); v3 = fmaxf(v3, 0.f);
            }
            if (r < n) {
                if (OUTHALF) {
                    *(uint32_t*)(outh + (size_t)r * DD + col) = packh2(v0, v1);
                } else {
                    *(float2*)(outf + (size_t)r * DD + col) = make_float2(v0, v1);
                }
            }
            if (r + 8 < n) {
                if (OUTHALF) {
                    *(uint32_t*)(outh + (size_t)(r + 8) * DD + col) = packh2(v2, v3);
                } else {
                    *(float2*)(outf + (size_t)(r + 8) * DD + col) = make_float2(v2, v3);
                }
            }
        }
    }
}

// ---------------------------------------------------------------------------
extern "C" void kernel_launch(void* const* d_in, const int* in_sizes, int n_in,
                              void* d_out, int out_size) {
    const float* x   = (const float*)d_in[0];
    const int* ei    = (const int*)d_in[1];
    const float* Wn1 = (const float*)d_in[2];
    const float* bn1 = (const float*)d_in[3];
    const float* Ws1 = (const float*)d_in[4];
    const float* bs1 = (const float*)d_in[5];
    const float* Wn2 = (const float*)d_in[6];
    const float* bn2 = (const float*)d_in[7];
    const float* Ws2 = (const float*)d_in[8];
    const float* bs2 = (const float*)d_in[9];
    float* out = (float*)d_out;

    const int n = in_sizes[0] / DD;
    const int E = in_sizes[1] / 2;
    const int* src = ei;
    const int* dst = ei + E;

    __half* d_xh;   cudaGetSymbolAddress((void**)&d_xh, g_xh);
    __half* d_h1h;  cudaGetSymbolAddress((void**)&d_h1h, g_h1h);
    __half* d_aggh; cudaGetSymbolAddress((void**)&d_aggh, g_aggh);
    __half* d_wh;   cudaGetSymbolAddress((void**)&d_wh, g_wh);
    float* d_bsum;  cudaGetSymbolAddress((void**)&d_bsum, g_bsum);

    const int threads = 256;
    const int nb = (n + 1023) / 1024;
    const int n8 = (n * DD) / 8;
    const int nbDeg = (E + 255) / 256;
    const int nbCvt = (n8 + 255) / 256;

    // --- prep (deg + x->fp16 + weights->fp16 + bias) + CSR build ---
    prep_kernel<<<nbDeg + nbCvt + 8, threads>>>(
        x, dst, E, n8, Wn1, Ws1, Wn2, Ws2, bn1, bs1, bn2, bs2, nbDeg, nbCvt);
    scanA_kernel<<<nb, 1024>>>(n);
    scanC_kernel<<<(n + 1 + threads - 1) / threads, threads>>>(n, nb);
    fill_kernel<<<(E + threads - 1) / threads, threads>>>(src, dst, E);

    const unsigned agg_blocks = ((unsigned)n * 32u + threads - 1) / threads;
    const int gemm_blocks = (n + 127) / 128;

    // layer 1: mean-aggregate x_h -> agg_h, GEMM + bias + relu -> h1 (fp16)
    agg_kernel<<<agg_blocks, threads>>>(d_xh, d_aggh, n);
    gemm_kernel<true, true><<<gemm_blocks, 256>>>(
        d_aggh, d_xh, d_wh, d_wh + 16384, d_bsum, nullptr, d_h1h, n);

    // layer 2: mean-aggregate h1_h -> agg_h, GEMM + bias -> out (fp32)
    agg_kernel<<<agg_blocks, threads>>>(d_h1h, d_aggh, n);
    gemm_kernel<false, false><<<gemm_blocks, 256>>>(
        d_aggh, d_h1h, d_wh + 2 * 16384, d_wh + 3 * 16384, d_bsum + DD, out, nullptr, n);
}

// round 14
// speedup vs baseline: 1.9252x; 1.0217x over previous
#include <cuda_runtime.h>
#include <cuda_fp16.h>
#include <cstdint>

#define NN 100000
#define DD 128
#define EE_MAX 1700000

// Scratch (allocation-free rule: __device__ globals)
__device__ __half g_xh[(size_t)NN * DD];     // fp16 copy of x
__device__ __half g_h1h[(size_t)NN * DD];    // fp16 h1 (only copy)
__device__ __half g_aggh[(size_t)NN * DD];   // fp16 aggregated means
__device__ __half g_wh[4 * 128 * 128];       // fp16 weights: Wn1,Ws1,Wn2,Ws2
__device__ float g_bsum[2][DD];              // bn+bs per layer
__device__ int   g_deg[NN];
__device__ int   g_cursor[NN];
__device__ int   g_rowptr[NN + 1];
__device__ int   g_col[EE_MAX];
__device__ int   g_partial[128];

// ---------------------------------------------------------------------------
__device__ __forceinline__ uint32_t packh2(float a, float b) {
    __half2 h = __floats2half2_rn(a, b);
    return *(uint32_t*)&h;
}

// Heterogeneous prep: deg histogram | x->fp16 | weights->fp16 + bias sums.
__global__ __launch_bounds__(256) void prep_kernel(
    const float* __restrict__ x, const int* __restrict__ dst, int E, int n8,
    const float* __restrict__ Wn1, const float* __restrict__ Ws1,
    const float* __restrict__ Wn2, const float* __restrict__ Ws2,
    const float* __restrict__ bn1, const float* __restrict__ bs1,
    const float* __restrict__ bn2, const float* __restrict__ bs2,
    int nbDeg, int nbCvt) {
    const int b = blockIdx.x;
    if (b < nbDeg) {
        const int e = b * 256 + threadIdx.x;
        if (e < E) atomicAdd(&g_deg[dst[e]], 1);
    } else if (b < nbDeg + nbCvt) {
        const int i = (b - nbDeg) * 256 + threadIdx.x;
        if (i < n8) {
            const float4* p = (const float4*)x + i * 2;
            const float4 v0 = p[0], v1 = p[1];
            uint4 o;
            o.x = packh2(v0.x, v0.y);
            o.y = packh2(v0.z, v0.w);
            o.z = packh2(v1.x, v1.y);
            o.w = packh2(v1.z, v1.w);
            ((uint4*)g_xh)[i] = o;
        }
    } else {
        const int bw = b - nbDeg - nbCvt;            // 0..7
        const int t0 = bw * 256 + threadIdx.x;       // 0..2047
#pragma unroll 1
        for (int i = t0; i < 8192; i += 2048) {      // 8192 uint4 = 65536 halves
            const int m = i >> 11;                   // matrix 0..3
            const int r = i & 2047;                  // uint4 index in matrix
            const float* W = (m == 0) ? Wn1 : (m == 1) ? Ws1 : (m == 2) ? Wn2 : Ws2;
            const float4* p = (const float4*)W + r * 2;
            const float4 v0 = p[0], v1 = p[1];
            uint4 o;
            o.x = packh2(v0.x, v0.y);
            o.y = packh2(v0.z, v0.w);
            o.z = packh2(v1.x, v1.y);
            o.w = packh2(v1.z, v1.w);
            ((uint4*)g_wh)[i] = o;
        }
        if (bw == 0 && threadIdx.x < 128) {
            g_bsum[0][threadIdx.x] = bn1[threadIdx.x] + bs1[threadIdx.x];
            g_bsum[1][threadIdx.x] = bn2[threadIdx.x] + bs2[threadIdx.x];
        }
    }
}

// Block-wise scan of g_deg -> g_rowptr (local exclusive) + block totals.
// Also re-zeros g_deg (next replay).
__global__ __launch_bounds__(1024) void scanA_kernel(int n) {
    const int i = blockIdx.x * 1024 + threadIdx.x;
    const int lane = threadIdx.x & 31;
    const int w = threadIdx.x >> 5;
    const int v = (i < n) ? g_deg[i] : 0;
    int s = v;
#pragma unroll
    for (int o = 1; o < 32; o <<= 1) {
        int t = __shfl_up_sync(0xffffffffu, s, o);
        if (lane >= o) s += t;
    }
    __shared__ int wsum[32];
    if (lane == 31) wsum[w] = s;
    __syncthreads();
    if (w == 0) {
        int ws = wsum[lane];
#pragma unroll
        for (int o = 1; o < 32; o <<= 1) {
            int t = __shfl_up_sync(0xffffffffu, ws, o);
            if (lane >= o) ws += t;
        }
        wsum[lane] = ws;
    }
    __syncthreads();
    const int excl = s - v + (w ? wsum[w - 1] : 0);
    if (i < n) {
        g_rowptr[i] = excl;
        g_deg[i] = 0;
    }
    if (threadIdx.x == 1023) g_partial[blockIdx.x] = excl + v;
}

// Adds the prefix of block totals; also seeds g_cursor with the final rowptr
// so fill_kernel needs no separate rowptr read.
__global__ __launch_bounds__(256) void scanC_kernel(int n, int nb) {
    __shared__ int red[256];
    const int t = threadIdx.x;
    const int r = blockIdx.x >> 2;
    red[t] = (t < r) ? g_partial[t] : 0;
    __syncthreads();
#pragma unroll
    for (int o = 128; o > 0; o >>= 1) {
        if (t < o) red[t] += red[t + o];
        __syncthreads();
    }
    const int S = red[0];
    const int i = blockIdx.x * 256 + t;
    if (i < n) {
        const int v = g_rowptr[i] + S;
        g_rowptr[i] = v;
        g_cursor[i] = v;
    }
    if (i == n) {
        int tot = 0;
        for (int j = 0; j < nb; j++) tot += g_partial[j];
        g_rowptr[n] = tot;
    }
}

__global__ void fill_kernel(const int* __restrict__ src, const int* __restrict__ dst, int E) {
    int e = blockIdx.x * blockDim.x + threadIdx.x;
    if (e < E) {
        const int p = atomicAdd(&g_cursor[dst[e]], 1);
        g_col[p] = src[e];
    }
}

// ---------------------------------------------------------------------------
// Paired-neighbor mean aggregation over fp16 features: one warp per node.
// Two warp halves process two neighbors at once; each lane loads uint4
// (8 halves = 16B); fp32 accumulation; fp16 pre-normalized output.
__global__ __launch_bounds__(256) void agg_kernel(const __half* __restrict__ feat,
                                                  __half* __restrict__ out, int n) {
    const int warp = (blockIdx.x * blockDim.x + threadIdx.x) >> 5;
    if (warp >= n) return;
    const int lane = threadIdx.x & 31;
    const int half = lane >> 4;
    const int l16 = lane & 15;
    const int c = l16 << 3;
    const int beg = g_rowptr[warp];
    const int end = g_rowptr[warp + 1];

    float a0 = 0.f, a1 = 0.f, a2 = 0.f, a3 = 0.f;
    float a4 = 0.f, a5 = 0.f, a6 = 0.f, a7 = 0.f;
    for (int base = beg; base < end; base += 32) {
        const int idx = base + lane;
        const int sv = (idx < end) ? g_col[idx] : 0;
        const int cnt = min(end - base, 32);
#pragma unroll 4
        for (int j = 0; j < cnt; j += 2) {
            const int jj = j + half;
            const int s = __shfl_sync(0xffffffffu, sv, jj);
            if (jj < cnt) {
                const uint4 u = *(const uint4*)(feat + (size_t)s * DD + c);
                float2 p;
                p = __half22float2(*(const __half2*)&u.x); a0 += p.x; a1 += p.y;
                p = __half22float2(*(const __half2*)&u.y); a2 += p.x; a3 += p.y;
                p = __half22float2(*(const __half2*)&u.z); a4 += p.x; a5 += p.y;
                p = __half22float2(*(const __half2*)&u.w); a6 += p.x; a7 += p.y;
            }
        }
    }
    a0 += __shfl_down_sync(0xffffffffu, a0, 16);
    a1 += __shfl_down_sync(0xffffffffu, a1, 16);
    a2 += __shfl_down_sync(0xffffffffu, a2, 16);
    a3 += __shfl_down_sync(0xffffffffu, a3, 16);
    a4 += __shfl_down_sync(0xffffffffu, a4, 16);
    a5 += __shfl_down_sync(0xffffffffu, a5, 16);
    a6 += __shfl_down_sync(0xffffffffu, a6, 16);
    a7 += __shfl_down_sync(0xffffffffu, a7, 16);
    if (half == 0) {
        const float inv = 1.0f / fmaxf((float)(end - beg), 1.0f);
        uint4 o;
        o.x = packh2(a0 * inv, a1 * inv);
        o.y = packh2(a2 * inv, a3 * inv);
        o.z = packh2(a4 * inv, a5 * inv);
        o.w = packh2(a6 * inv, a7 * inv);
        *(uint4*)(out + (size_t)warp * DD + c) = o;
    }
}

// ---------------------------------------------------------------------------
// FP16 mma.sync (m16n8k16, fp32 accumulate) fused GEMM + bias(+relu),
// fragments loaded via ldmatrix.m8n8.x4.
// out[r][o] = relu?( A1[r][:] @ Wn[o][:] + A2[r][:] @ Ws[o][:] + bsum[o] )
// SMEM tile: [k2b (0..3)][row (0..127)] 16B blocks; k2b stride 2080 B.
__device__ __forceinline__ void mma_f16(float* d, const uint32_t* a, const uint32_t* b) {
    asm volatile(
        "mma.sync.aligned.m16n8k16.row.col.f32.f16.f16.f32 "
        "{%0,%1,%2,%3}, {%4,%5,%6,%7}, {%8,%9}, {%0,%1,%2,%3};"
        : "+f"(d[0]), "+f"(d[1]), "+f"(d[2]), "+f"(d[3])
        : "r"(a[0]), "r"(a[1]), "r"(a[2]), "r"(a[3]), "r"(b[0]), "r"(b[1]));
}
#define LDSM_X4(r0, r1, r2, r3, addr)                                          \
    asm volatile("ldmatrix.sync.aligned.m8n8.x4.shared.b16 {%0,%1,%2,%3}, [%4];" \
                 : "=r"(r0), "=r"(r1), "=r"(r2), "=r"(r3) : "r"(addr))

template <bool RELU, bool OUTHALF>
__global__ __launch_bounds__(256) void gemm_kernel(
    const __half* __restrict__ A1, const __half* __restrict__ A2,
    const __half* __restrict__ Wnh, const __half* __restrict__ Wsh,
    const float* __restrict__ bsum,
    float* __restrict__ outf, __half* __restrict__ outh, int n) {
    __shared__ uint32_t sA[4 * 520];
    __shared__ uint32_t sB[4 * 520];

    const int tid = threadIdx.x;
    const int wid = tid >> 5;
    const int lane = tid & 31;
    const int g = lane >> 2;
    const int c = lane & 3;
    const int block_row = blockIdx.x * 128;
    const int m0 = (wid >> 2) * 64;
    const int n0 = (wid & 3) * 32;

    const uint32_t sA_u = (uint32_t)__cvta_generic_to_shared(sA);
    const uint32_t sB_u = (uint32_t)__cvta_generic_to_shared(sB);
    const int lg = lane >> 3;       // matrix id 0..3
    const int lr = lane & 7;        // row within 8x8 matrix
    // A x4: m0/m1 = row-halves @ kb0, m2/m3 = row-halves @ kb1
    const uint32_t aAddr0 = sA_u + (uint32_t)(lg >> 1) * 2080u
                          + (uint32_t)(m0 + (lg & 1) * 8 + lr) * 16u;
    // B x4 over nt-pair: m0=(nt,kb0), m1=(nt,kb1), m2=(nt+1,kb0), m3=(nt+1,kb1)
    const uint32_t bAddr0 = sB_u + (uint32_t)(lg & 1) * 2080u
                          + (uint32_t)(n0 + (lg >> 1) * 8 + lr) * 16u;

    float acc[4][4][4];
#pragma unroll
    for (int mt = 0; mt < 4; mt++)
#pragma unroll
        for (int nt = 0; nt < 4; nt++)
#pragma unroll
            for (int q = 0; q < 4; q++) acc[mt][nt][q] = 0.f;

    for (int c0 = 0; c0 < 256; c0 += 32) {
        const __half* aptr = (c0 < 128)
            ? (A1 + (size_t)block_row * DD + c0)
            : (A2 + (size_t)block_row * DD + (c0 - 128));
        const __half* bptr = (c0 < 128) ? (Wnh + c0) : (Wsh + (c0 - 128));

        if (c0) __syncthreads();
#pragma unroll
        for (int i = 0; i < 2; i++) {
            const int s2 = i * 256 + tid;     // 0..511
            const int row = s2 >> 2;          // 0..127
            const int k2b = s2 & 3;           // 8-k block within chunk
            const int so = k2b * 520 + row * 4;

            uint4 h = make_uint4(0u, 0u, 0u, 0u);
            if (block_row + row < n)
                h = *(const uint4*)(aptr + (size_t)row * DD + k2b * 8);
            *(uint4*)(sA + so) = h;

            const uint4 w = *(const uint4*)(bptr + (size_t)row * 128 + k2b * 8);
            *(uint4*)(sB + so) = w;
        }
        __syncthreads();

#pragma unroll
        for (int st = 0; st < 2; st++) {      // two k16 steps per 32-chunk
            const uint32_t stoff = (uint32_t)st * 4160u;
            uint32_t Ar[4][4], Br[2][4];
#pragma unroll
            for (int mt = 0; mt < 4; mt++)
                LDSM_X4(Ar[mt][0], Ar[mt][1], Ar[mt][2], Ar[mt][3],
                        aAddr0 + stoff + (uint32_t)(mt * 256));
#pragma unroll
            for (int np = 0; np < 2; np++)
                LDSM_X4(Br[np][0], Br[np][1], Br[np][2], Br[np][3],
                        bAddr0 + stoff + (uint32_t)(np * 256));
#pragma unroll
            for (int mt = 0; mt < 4; mt++)
#pragma unroll
                for (int nt = 0; nt < 4; nt++)
                    mma_f16(acc[mt][nt], Ar[mt], &Br[nt >> 1][(nt & 1) * 2]);
        }
    }

    // Epilogue: bias + optional relu
#pragma unroll
    for (int nt = 0; nt < 4; nt++) {
        const int col = n0 + nt * 8 + 2 * c;
        const float b0v = bsum[col];
        const float b1v = bsum[col + 1];
#pragma unroll
        for (int mt = 0; mt < 4; mt++) {
            const int r = block_row + m0 + mt * 16 + g;
            float v0 = acc[mt][nt][0] + b0v;
            float v1 = acc[mt][nt][1] + b1v;
            float v2 = acc[mt][nt][2] + b0v;
            float v3 = acc[mt][nt][3] + b1v;
            if (RELU) {
                v0 = fmaxf(v0, 0.f); v1 = fmaxf(v1, 0.f);
                v2 = fmaxf(v2, 0.f); v3 = fmaxf(v3, 0.f);
            }
            if (r < n) {
                if (OUTHALF) {
                    *(uint32_t*)(outh + (size_t)r * DD + col) = packh2(v0, v1);
                } else {
                    *(float2*)(outf + (size_t)r * DD + col) = make_float2(v0, v1);
                }
            }
            if (r + 8 < n) {
                if (OUTHALF) {
                    *(uint32_t*)(outh + (size_t)(r + 8) * DD + col) = packh2(v2, v3);
                } else {
                    *(float2*)(outf + (size_t)(r + 8) * DD + col) = make_float2(v2, v3);
                }
            }
        }
    }
}

// ---------------------------------------------------------------------------
extern "C" void kernel_launch(void* const* d_in, const int* in_sizes, int n_in,
                              void* d_out, int out_size) {
    const float* x   = (const float*)d_in[0];
    const int* ei    = (const int*)d_in[1];
    const float* Wn1 = (const float*)d_in[2];
    const float* bn1 = (const float*)d_in[3];
    const float* Ws1 = (const float*)d_in[4];
    const float* bs1 = (const float*)d_in[5];
    const float* Wn2 = (const float*)d_in[6];
    const float* bn2 = (const float*)d_in[7];
    const float* Ws2 = (const float*)d_in[8];
    const float* bs2 = (const float*)d_in[9];
    float* out = (float*)d_out;

    const int n = in_sizes[0] / DD;
    const int E = in_sizes[1] / 2;
    const int* src = ei;
    const int* dst = ei + E;

    __half* d_xh;   cudaGetSymbolAddress((void**)&d_xh, g_xh);
    __half* d_h1h;  cudaGetSymbolAddress((void**)&d_h1h, g_h1h);
    __half* d_aggh; cudaGetSymbolAddress((void**)&d_aggh, g_aggh);
    __half* d_wh;   cudaGetSymbolAddress((void**)&d_wh, g_wh);
    float* d_bsum;  cudaGetSymbolAddress((void**)&d_bsum, g_bsum);

    const int threads = 256;
    const int nb = (n + 1023) / 1024;
    const int n8 = (n * DD) / 8;
    const int nbDeg = (E + 255) / 256;
    const int nbCvt = (n8 + 255) / 256;

    // --- prep (deg + x->fp16 + weights->fp16 + bias) + CSR build ---
    prep_kernel<<<nbDeg + nbCvt + 8, threads>>>(
        x, dst, E, n8, Wn1, Ws1, Wn2, Ws2, bn1, bs1, bn2, bs2, nbDeg, nbCvt);
    scanA_kernel<<<nb, 1024>>>(n);
    scanC_kernel<<<(n + 1 + threads - 1) / threads, threads>>>(n, nb);
    fill_kernel<<<(E + threads - 1) / threads, threads>>>(src, dst, E);

    const unsigned agg_blocks = ((unsigned)n * 32u + threads - 1) / threads;
    const int gemm_blocks = (n + 127) / 128;

    // layer 1: mean-aggregate x_h -> agg_h, GEMM + bias + relu -> h1 (fp16)
    agg_kernel<<<agg_blocks, threads>>>(d_xh, d_aggh, n);
    gemm_kernel<true, true><<<gemm_blocks, 256>>>(
        d_aggh, d_xh, d_wh, d_wh + 16384, d_bsum, nullptr, d_h1h, n);

    // layer 2: mean-aggregate h1_h -> agg_h, GEMM + bias -> out (fp32)
    agg_kernel<<<agg_blocks, threads>>>(d_h1h, d_aggh, n);
    gemm_kernel<false, false><<<gemm_blocks, 256>>>(
        d_aggh, d_h1h, d_wh + 2 * 16384, d_wh + 3 * 16384, d_bsum + DD, out, nullptr, n);
}